// round 10
// baseline (speedup 1.0000x reference)
#include <cuda_runtime.h>
#include <cuda_fp16.h>
#include <math_constants.h>

// ---------------- problem constants ----------------
#define BATCH   32
#define Q_LEN   32
#define HID     128
#define DOC_LEN 128
#define K_CAND  256
#define K_OUT   16
#define N_PIDS  20000
#define N_EMB   (N_PIDS * DOC_LEN)

// fp16 chunk tile pitch: 40 halves (80 B) -> 20-bank row stride: 8 consecutive
// rows cover all 32 banks => conflict-free ldmatrix AND STS.64.
#define HPITCH_U32 20            // pitch in u32 (40 halves)

typedef unsigned long long u64;
typedef unsigned int u32;

// ---------------- device scratch ----------------
__device__ int    g_upids[BATCH * K_CAND];
__device__ int    g_ucnt[BATCH];
__device__ float  g_scores[BATCH * K_CAND];
__device__ uint2  g_qfh[BATCH * 8 * 4 * 32];
__device__ uint2  g_qfl[BATCH * 8 * 4 * 32];
__device__ int    g_ready[BATCH];   // zero-init; reset by topk CTA each launch
__device__ int    g_done[BATCH];    // zero-init; reset by topk CTA each launch

// ---------------- helpers ----------------
__device__ __forceinline__ void split_h2(float2 v, u32& hi, u32& lo) {
    __half2 h = __float22half2_rn(v);
    float2 hf = __half22float2(h);
    __half2 l = __float22half2_rn(make_float2(v.x - hf.x, v.y - hf.y));
    hi = *reinterpret_cast<u32*>(&h);
    lo = *reinterpret_cast<u32*>(&l);
}
__device__ __forceinline__ void mma16(float* c, const u32* a, const u32* b) {
    asm volatile(
        "mma.sync.aligned.m16n8k16.row.col.f32.f16.f16.f32 "
        "{%0,%1,%2,%3}, {%4,%5,%6,%7}, {%8,%9}, {%0,%1,%2,%3};"
        : "+f"(c[0]), "+f"(c[1]), "+f"(c[2]), "+f"(c[3])
        : "r"(a[0]), "r"(a[1]), "r"(a[2]), "r"(a[3]), "r"(b[0]), "r"(b[1]));
}
__device__ __forceinline__ void ldmx4(u32* r, u32 addr) {
    asm volatile(
        "ldmatrix.sync.aligned.m8n8.x4.shared.b16 {%0,%1,%2,%3}, [%4];"
        : "=r"(r[0]), "=r"(r[1]), "=r"(r[2]), "=r"(r[3]) : "r"(addr));
}
// monotone map: ascending u32 <=> ascending float (works for -inf)
__device__ __forceinline__ u32 fmap(float f) {
    u32 s = __float_as_uint(f);
    return (s & 0x80000000u) ? ~s : (s | 0x80000000u);
}

// ================= fused kernel =================
// grid: 8192 CTAs, bid = slot*32 + b, 128 threads.
// slot==0 CTAs (bids 0..31, wave 1) run dedup+qprep for batch b, then score.
// Others spin on g_ready[b]. Per-batch done counter; 256th CTA runs top-16.
__global__ void __launch_bounds__(128, 3)
fused_kernel(const void* __restrict__ idx_raw,
             const float* __restrict__ qv,
             const float* __restrict__ vectors,
             float* __restrict__ out, int out_size) {
    __shared__ u32 sHI[2][DOC_LEN * HPITCH_U32];   // 10 KB x2
    __shared__ u32 sLO[2][DOC_LEN * HPITCH_U32];   // 10 KB x2
    __shared__ float red[4 * 32];
    __shared__ int  pids[K_CAND];
    __shared__ int  swsum[8];
    __shared__ int  s_ok;
    __shared__ int  s_last;
    __shared__ u64  keys[K_CAND];

    const int bid  = blockIdx.x;
    const int b    = bid & 31;
    const int slot = bid >> 5;
    const int tid  = threadIdx.x;
    const int wid  = tid >> 5;
    const int lane = tid & 31;

    // ---------------- phase A: prep (slot 0) or spin ----------------
    if (slot == 0) {
        // dtype detect (128 int64 words; in-bounds for both layouts)
        if (tid == 0) s_ok = 1;
        __syncthreads();
        {
            long long v = ((const long long*)idx_raw)[b * 128 + tid];
            if (v < 0 || v >= (long long)N_EMB) atomicAnd(&s_ok, 0);
        }
        __syncthreads();
        const int is64 = s_ok;

        // load pids (2 per thread)
#pragma unroll
        for (int h = 0; h < 2; h++) {
            int i = 128 * h + tid;
            long long v;
            if (is64) v = ((const long long*)idx_raw)[b * K_CAND + i];
            else      v = (long long)(((const int*)idx_raw)[b * K_CAND + i]);
            pids[i] = (int)(v >> 7);   // emb2pid[i] == i / 128
        }
        __syncthreads();

        // bitonic sort ascending, 256 elems, 128 threads (XOR pairs disjoint)
        for (int k = 2; k <= K_CAND; k <<= 1) {
            for (int j = k >> 1; j > 0; j >>= 1) {
#pragma unroll
                for (int h = 0; h < 2; h++) {
                    int i = 128 * h + tid;
                    int ixj = i ^ j;
                    if (ixj > i) {
                        int a = pids[i], c = pids[ixj];
                        bool up = ((i & k) == 0);
                        if ((a > c) == up) { pids[i] = c; pids[ixj] = a; }
                    }
                }
                __syncthreads();
            }
        }

        // stable compaction of unique values (two halves)
        int myv0 = pids[tid], myv1 = pids[tid + 128];
        int f0 = (tid == 0) || (myv0 != pids[tid - 1]);
        int f1 = (myv1 != pids[tid + 127]);
        unsigned m0 = __ballot_sync(0xffffffffu, f0);
        unsigned m1 = __ballot_sync(0xffffffffu, f1);
        if (lane == 0) { swsum[wid] = __popc(m0); swsum[4 + wid] = __popc(m1); }
        __syncthreads();
        int pref[8], run = 0;
#pragma unroll
        for (int s = 0; s < 8; s++) { pref[s] = run; run += swsum[s]; }
        unsigned lt = (1u << lane) - 1;
        int pos0 = pref[wid] + __popc(m0 & lt);
        int pos1 = pref[4 + wid] + __popc(m1 & lt);
        if (f0) g_upids[b * K_CAND + pos0] = myv0;
        if (f1) g_upids[b * K_CAND + pos1] = myv1;
        if (tid == 127) g_ucnt[b] = pos1 + f1;

        // qprep: pre-split fp16 hi/lo B fragments
        {
            const float* src = qv + (size_t)b * Q_LEN * HID;
            uint2* dh = g_qfh + (size_t)b * (8 * 4 * 32);
            uint2* dl = g_qfl + (size_t)b * (8 * 4 * 32);
            for (int idx = tid; idx < 8 * 4 * 32; idx += 128) {
                int s  = idx >> 7;
                int tt = (idx >> 5) & 3;
                int l  = idx & 31;
                int n  = 8 * tt + (l >> 2);
                int k0 = 16 * s + 2 * (l & 3);
                u32 b0h, b0l, b1h, b1l;
                split_h2(make_float2(src[n * HID + k0],     src[n * HID + k0 + 1]), b0h, b0l);
                split_h2(make_float2(src[n * HID + k0 + 8], src[n * HID + k0 + 9]), b1h, b1l);
                dh[idx] = make_uint2(b0h, b1h);
                dl[idx] = make_uint2(b0l, b1l);
            }
        }
        __syncthreads();
        __threadfence();
        if (tid == 0) atomicExch(&g_ready[b], 1);
    } else {
        if (tid == 0) {
            while (atomicAdd(&g_ready[b], 0) == 0) __nanosleep(64);
        }
        __syncthreads();     // all threads wait; atomic RMW read = coherent
    }

    // ---------------- phase B: scoring ----------------
    const int cnt = g_ucnt[b];
    if (slot < cnt) {
        const int pid = g_upids[b * K_CAND + slot];
        const float* doc = vectors + (size_t)pid * DOC_LEN * HID;

        const int srow0 = tid >> 3;
        const int scol4 = 4 * (tid & 7);

        float4 bufA[8], bufB[8];
#pragma unroll
        for (int r = 0; r < 8; r++)
            bufA[r] = __ldg((const float4*)(doc + (16 * r + srow0) * HID + 0 * 32 + scol4));
#pragma unroll
        for (int r = 0; r < 8; r++)
            bufB[r] = __ldg((const float4*)(doc + (16 * r + srow0) * HID + 1 * 32 + scol4));

        const uint2* qfh = g_qfh + (size_t)b * (8 * 4 * 32) + lane;
        const uint2* qfl = g_qfl + (size_t)b * (8 * 4 * 32) + lane;
        const u32 hibase0 = (u32)__cvta_generic_to_shared(&sHI[0][0]);
        const u32 hibase1 = (u32)__cvta_generic_to_shared(&sHI[1][0]);
        const u32 lobase0 = (u32)__cvta_generic_to_shared(&sLO[0][0]);
        const u32 lobase1 = (u32)__cvta_generic_to_shared(&sLO[1][0]);

        float acc[2][4][4];
#pragma unroll
        for (int mt = 0; mt < 2; mt++)
#pragma unroll
            for (int t = 0; t < 4; t++)
#pragma unroll
                for (int r = 0; r < 4; r++) acc[mt][t][r] = 0.0f;

        const u32 lm_row = (u32)(lane & 15) * (HPITCH_U32 * 4);
        const u32 lm_col = (u32)(lane >> 4) * 16;

#pragma unroll
        for (int c = 0; c < 4; c++) {
            const int bsel = c & 1;
            const u32 hib = bsel ? hibase1 : hibase0;
            const u32 lob = bsel ? lobase1 : lobase0;
            u32* Hd = sHI[bsel];
            u32* Ld = sLO[bsel];

#pragma unroll
            for (int r = 0; r < 8; r++) {
                float4 v = (c & 1) ? bufB[r] : bufA[r];
                u32 h0, l0, h1, l1;
                split_h2(make_float2(v.x, v.y), h0, l0);
                split_h2(make_float2(v.z, v.w), h1, l1);
                int u = (16 * r + srow0) * HPITCH_U32 + (scol4 >> 1);
                *(uint2*)(Hd + u) = make_uint2(h0, h1);
                *(uint2*)(Ld + u) = make_uint2(l0, l1);
            }
            if (c < 2) {
#pragma unroll
                for (int r = 0; r < 8; r++) {
                    float4 v = __ldg((const float4*)(doc + (16 * r + srow0) * HID
                                                     + (c + 2) * 32 + scol4));
                    if (c & 1) bufB[r] = v; else bufA[r] = v;
                }
            }
            __syncthreads();

#pragma unroll
            for (int si = 0; si < 2; si++) {
                const int s = 2 * c + si;
                uint2 qh[4], ql[4];
#pragma unroll
                for (int t = 0; t < 4; t++) {
                    qh[t] = __ldg(&qfh[(s * 4 + t) * 32]);
                    ql[t] = __ldg(&qfl[(s * 4 + t) * 32]);
                }
                u32 ahi[2][4], alo[2][4];
#pragma unroll
                for (int mt = 0; mt < 2; mt++) {
                    u32 off = (u32)((32 * wid + 16 * mt) * (HPITCH_U32 * 4))
                            + lm_row + 32 * si + lm_col;
                    ldmx4(ahi[mt], hib + off);
                    ldmx4(alo[mt], lob + off);
                }
#pragma unroll
                for (int t = 0; t < 4; t++) {
                    u32 bh[2] = { qh[t].x, qh[t].y };
                    u32 bl[2] = { ql[t].x, ql[t].y };
#pragma unroll
                    for (int mt = 0; mt < 2; mt++) {
                        mma16(acc[mt][t], ahi[mt], bh);
                        mma16(acc[mt][t], ahi[mt], bl);
                        mma16(acc[mt][t], alo[mt], bh);
                    }
                }
            }
            __syncthreads();
        }

        // per-q max over this warp's 32 docs
#pragma unroll
        for (int t = 0; t < 4; t++) {
            float mx0 = fmaxf(acc[0][t][0], acc[0][t][2]);
            mx0 = fmaxf(mx0, fmaxf(acc[1][t][0], acc[1][t][2]));
            float mx1 = fmaxf(acc[0][t][1], acc[0][t][3]);
            mx1 = fmaxf(mx1, fmaxf(acc[1][t][1], acc[1][t][3]));
#pragma unroll
            for (int o = 4; o <= 16; o <<= 1) {
                mx0 = fmaxf(mx0, __shfl_xor_sync(0xffffffffu, mx0, o));
                mx1 = fmaxf(mx1, __shfl_xor_sync(0xffffffffu, mx1, o));
            }
            if (lane < 4) {
                red[wid * 32 + 8 * t + 2 * lane + 0] = mx0;
                red[wid * 32 + 8 * t + 2 * lane + 1] = mx1;
            }
        }
        __syncthreads();

        if (wid == 0) {
            float m = fmaxf(fmaxf(red[lane], red[32 + lane]),
                            fmaxf(red[64 + lane], red[96 + lane]));
#pragma unroll
            for (int o = 16; o > 0; o >>= 1)
                m += __shfl_xor_sync(0xffffffffu, m, o);
            if (lane == 0)
                g_scores[b * K_CAND + slot] = m * (1.0f / (float)Q_LEN);
        }
    } else {
        if (tid == 0) g_scores[b * K_CAND + slot] = -CUDART_INF_F;
    }

    // ---------------- phase C: done-count; last CTA does top-16 ------------
    __threadfence();
    if (tid == 0) {
        int old = atomicAdd(&g_done[b], 1);
        s_last = (old == K_CAND - 1);
    }
    __syncthreads();
    if (!s_last) return;

    // two elements per thread
#pragma unroll
    for (int h = 0; h < 2; h++) {
        int i = 128 * h + tid;
        float sc = g_scores[b * K_CAND + i];
        keys[i] = ((u64)(~fmap(sc)) << 32) | (u32)i;
    }
    __syncthreads();
    for (int k = 2; k <= K_CAND; k <<= 1) {
        for (int j = k >> 1; j > 0; j >>= 1) {
#pragma unroll
            for (int h = 0; h < 2; h++) {
                int i = 128 * h + tid;
                int ixj = i ^ j;
                if (ixj > i) {
                    u64 a = keys[i], c = keys[ixj];
                    bool up = ((i & k) == 0);
                    if ((a > c) == up) { keys[i] = c; keys[ixj] = a; }
                }
            }
            __syncthreads();
        }
    }
    if (tid < K_OUT) {
        int slotw = (int)(keys[tid] & 0xffffffffu);
        out[b * K_OUT + tid] = (float)g_upids[b * K_CAND + slotw];
        if (out_size >= BATCH * K_OUT * 2)
            out[BATCH * K_OUT + b * K_OUT + tid] = g_scores[b * K_CAND + slotw];
    }
    if (tid == 0) { g_done[b] = 0; g_ready[b] = 0; }   // restore for next replay
}

// ---------------- launcher ----------------
extern "C" void kernel_launch(void* const* d_in, const int* in_sizes, int n_in,
                              void* d_out, int out_size) {
    int qi = 0, ii = 1, vi = 3;
    for (int i = 0; i < n_in; i++) {
        if (in_sizes[i] == BATCH * Q_LEN * HID)            qi = i;
        else if (in_sizes[i] == BATCH * K_CAND)            ii = i;
        else if (in_sizes[i] == N_PIDS * DOC_LEN * HID)    vi = i;
    }
    const float* q       = (const float*)d_in[qi];
    const void*  idx     = d_in[ii];
    const float* vectors = (const float*)d_in[vi];

    fused_kernel<<<BATCH * K_CAND, 128>>>(idx, q, vectors,
                                          (float*)d_out, out_size);
}